// round 6
// baseline (speedup 1.0000x reference)
#include <cuda_runtime.h>
#include <cuda_bf16.h>
#include <stdint.h>

// ---------------- configuration ----------------
#define THREADS   512
#define NW        16                   // warps per block
#define TILE      4096                 // rows per block
#define PAIRS     4                    // row-pairs per thread (4*2*512 = 4096)
#define NCHUNK    (PAIRS * NW)         // 64 ballot-chunks per counter
#define MAXB      16384
#define TH        0.35f

#define FLAG_A    (1u << 30)
#define FLAG_P    (2u << 30)
#define VALMASK   0x3FFFFFFFu

// ---------------- device scratch ----------------
__device__ unsigned g_stat [MAXB];
__device__ unsigned g_statF[MAXB];
__device__ int      g_total[2];

// ---------------- K1: fused count + decoupled-lookback scan + stable scatter ----------------
__global__ void __launch_bounds__(THREADS)
fused_kernel(const float4* __restrict__ q, float* __restrict__ out,
             int R, unsigned roisN, int B) {
    __shared__ unsigned mlo[PAIRS][NW], mhi[PAIRS][NW];
    __shared__ unsigned mloF[PAIRS][NW], mhiF[PAIRS][NW];
    __shared__ unsigned co[NCHUNK], coF[NCHUNK];

    int b = blockIdx.x, t = threadIdx.x;
    int lane = t & 31, warp = t >> 5;
    unsigned lt = (1u << lane) - 1u;
    int pairBase = b * (TILE / 2);

    // -------- phase 1: load pairs into registers, ballot --------
    float4 v0[PAIRS], v1[PAIRS], v2[PAIRS];
#pragma unroll
    for (int k = 0; k < PAIRS; k++) {
        int p = pairBase + k * THREADS + t;
        int r0 = 2 * p;
        float4 a = make_float4(1.f, 0.f, 0.f, 0.f);
        float4 c = make_float4(0.f, -1.f, 1.f, 0.f);
        float4 d = make_float4(0.f, 0.f, 0.f, -1.f);
        if (r0 < R) {
            const float4* g = q + (size_t)p * 3;
            a = __ldg(g + 0); c = __ldg(g + 1); d = __ldg(g + 2);
        }
        v0[k] = a; v1[k] = c; v2[k] = d;
        // pair = [cls0,b00,b01,b02 | b03,sc0, cls1,b10 | b11,b12,b13,sc1]
        bool f0 = (r0 < R)     && (c.y >= TH);
        bool f1 = (r0 + 1 < R) && (d.w >= TH);
        bool p0 = f0 && (a.x == 0.0f);
        bool p1 = f1 && (c.z == 0.0f);
        unsigned blo  = __ballot_sync(0xffffffffu, p0);
        unsigned bhi  = __ballot_sync(0xffffffffu, p1);
        unsigned bFlo = __ballot_sync(0xffffffffu, f0);
        unsigned bFhi = __ballot_sync(0xffffffffu, f1);
        if (lane == 0) {
            mlo[k][warp] = blo;   mhi[k][warp] = bhi;
            mloF[k][warp] = bFlo; mhiF[k][warp] = bFhi;
        }
    }
    __syncthreads();

    // -------- phase 2: warps 0/1 scan 64 chunks + warp-parallel lookback --------
    if (warp < 2) {
        unsigned* stat = (warp == 0) ? g_stat : g_statF;
        // lane handles chunks 2*lane and 2*lane+1 (chunk id = k*NW + w)
        int c0 = 2 * lane, c1 = 2 * lane + 1;
        int k0 = c0 >> 4, w0 = c0 & 15;
        int k1 = c1 >> 4, w1 = c1 & 15;
        unsigned cnt0, cnt1;
        if (warp == 0) {
            cnt0 = __popc(mlo[k0][w0]) + __popc(mhi[k0][w0]);
            cnt1 = __popc(mlo[k1][w1]) + __popc(mhi[k1][w1]);
        } else {
            cnt0 = __popc(mloF[k0][w0]) + __popc(mhiF[k0][w0]);
            cnt1 = __popc(mloF[k1][w1]) + __popc(mhiF[k1][w1]);
        }
        unsigned pairCnt = cnt0 + cnt1;
        unsigned s = pairCnt;
#pragma unroll
        for (int o = 1; o < 32; o <<= 1) {
            unsigned n = __shfl_up_sync(0xffffffffu, s, o);
            if (lane >= o) s += n;
        }
        unsigned agg = __shfl_sync(0xffffffffu, s, 31);

        unsigned excl = 0;
        if (b == 0) {
            if (lane == 0) atomicExch(&stat[0], FLAG_P | agg);
        } else {
            if (lane == 0) atomicExch(&stat[b], FLAG_A | agg);
            int idx = b - 1 - lane;            // lane 0 = closest predecessor
            for (;;) {
                unsigned s2;
                if (idx >= 0) {
                    do { s2 = *(volatile unsigned*)&stat[idx]; }
                    while ((s2 >> 30) == 0u);
                } else {
                    s2 = FLAG_P;
                }
                unsigned pmask = __ballot_sync(0xffffffffu, (s2 >> 30) == 2u);
                if (pmask) {
                    int first = __ffs(pmask) - 1;
                    unsigned v = (lane <= first) ? (s2 & VALMASK) : 0u;
                    excl += __reduce_add_sync(0xffffffffu, v);
                    break;
                } else {
                    excl += __reduce_add_sync(0xffffffffu, s2 & VALMASK);
                    idx -= 32;
                }
            }
            if (lane == 0) atomicExch(&stat[b], FLAG_P | (excl + agg));
        }
        unsigned* dst = (warp == 0) ? co : coF;
        unsigned base0 = excl + s - pairCnt;
        dst[c0] = base0;
        dst[c1] = base0 + cnt0;
        if (b == B - 1 && lane == 0) {
            unsigned total = excl + agg;
            g_total[warp] = (int)total;
            out[11u * (size_t)(roisN / 5u) + warp] = (float)total;
        }
    }
    __syncthreads();

    // -------- phase 3: stable scatter from registers --------
    float2* __restrict__ outFull2 = reinterpret_cast<float2*>(out + roisN);
#pragma unroll
    for (int k = 0; k < PAIRS; k++) {
        unsigned blo  = mlo[k][warp],  bhi  = mhi[k][warp];
        unsigned bFlo = mloF[k][warp], bFhi = mhiF[k][warp];
        unsigned baseT = co[k * NW + warp], baseF = coF[k * NW + warp];
        unsigned preT = __popc(blo & lt) + __popc(bhi & lt);
        unsigned preF = __popc(bFlo & lt) + __popc(bFhi & lt);
        float4 a = v0[k], c = v1[k], d = v2[k];
        // row 0 of pair
        if ((bFlo >> lane) & 1u) {
            float2* oF = outFull2 + (size_t)(baseF + preF) * 3;
            oF[0] = make_float2(a.x, a.y);
            oF[1] = make_float2(a.z, a.w);
            oF[2] = make_float2(c.x, c.y);
            if ((blo >> lane) & 1u) {
                float* o = out + (size_t)(baseT + preT) * 5;
                o[0] = 0.0f; o[1] = a.y; o[2] = a.z; o[3] = a.w; o[4] = c.x;
            }
        }
        // row 1 of pair
        if ((bFhi >> lane) & 1u) {
            unsigned posF = baseF + preF + ((bFlo >> lane) & 1u);
            float2* oF = outFull2 + (size_t)posF * 3;
            oF[0] = make_float2(c.z, c.w);
            oF[1] = make_float2(d.x, d.y);
            oF[2] = make_float2(d.z, d.w);
            if ((bhi >> lane) & 1u) {
                unsigned pos = baseT + preT + ((blo >> lane) & 1u);
                float* o = out + (size_t)pos * 5;
                o[0] = 0.0f; o[1] = c.w; o[2] = d.x; o[3] = d.y; o[4] = d.z;
            }
        }
    }
}

// ---------------- K2: zero the dynamic tails + reset lookback state ----------------
__global__ void __launch_bounds__(256)
zero_tail_kernel(float* __restrict__ out, unsigned R, int B) {
    unsigned roisN = 5u * R;
    unsigned fullN = 6u * R;
    unsigned blockBase = blockIdx.x * 4096u;
    const float4 z4 = make_float4(0.f, 0.f, 0.f, 0.f);
    unsigned zsT = (unsigned)g_total[0] * 5u;
    unsigned zsF = (unsigned)g_total[1] * 6u;

#pragma unroll
    for (int j = 0; j < 4; j++) {
        unsigned f = blockBase + (unsigned)j * 1024u + threadIdx.x * 4u;
        if (f < roisN) {
            if (f + 4u <= zsT) continue;
            if (f >= zsT) {
                *reinterpret_cast<float4*>(out + f) = z4;
            } else {
                for (unsigned x = zsT; x < f + 4u; x++) out[x] = 0.0f;
            }
        } else {
            unsigned g = f - roisN;
            if (g >= fullN) continue;
            if (g + 4u <= zsF) continue;
            float* o = out + roisN;
            if (g >= zsF) {
                *reinterpret_cast<float4*>(o + g) = z4;
            } else {
                for (unsigned x = zsF; x < g + 4u; x++) o[x] = 0.0f;
            }
        }
    }
    // reset lookback statuses for the next replay
    int gi = blockIdx.x * 256 + threadIdx.x;
    if (gi < B) { g_stat[gi] = 0u; g_statF[gi] = 0u; }
}

// ---------------- launch ----------------
extern "C" void kernel_launch(void* const* d_in, const int* in_sizes, int n_in,
                              void* d_out, int out_size) {
    const float* det = (const float*)d_in[0];
    float* out = (float*)d_out;

    int R = in_sizes[0] / 6;                 // detections: (1, R, 6)
    int B = (R + TILE - 1) / TILE;           // 1024 for R = 4M
    unsigned roisN = 5u * (unsigned)R;

    fused_kernel<<<B, THREADS>>>((const float4*)det, out, R, roisN, B);

    unsigned totalFloats = 11u * (unsigned)R;
    unsigned zblocks = (totalFloats + 4095u) / 4096u;
    zero_tail_kernel<<<zblocks, 256>>>(out, (unsigned)R, B);
}

// round 7
// speedup vs baseline: 1.1878x; 1.1878x over previous
#include <cuda_runtime.h>
#include <cuda_bf16.h>
#include <stdint.h>

// ---------------- configuration ----------------
#define THREADS   256
#define TILE      1024                 // rows per block
#define PAIRS     2                    // row-pairs per thread (2*2*256 = 1024)
#define MAXB      16384
#define TH        0.35f

#define FLAG_A    (1u << 30)
#define FLAG_P    (2u << 30)
#define VALMASK   0x3FFFFFFFu

// ---------------- device scratch ----------------
// lookback status: [31:30]=flag, [29:0]=count. Zeroed by zero_tail for next replay.
__device__ unsigned g_stat [MAXB];
__device__ unsigned g_statF[MAXB];
__device__ int      g_total[2];

// ---------------- K1: fused count + decoupled-lookback scan + stable scatter ----------------
__global__ void __launch_bounds__(THREADS)
fused_kernel(const float4* __restrict__ q, float* __restrict__ out,
             int R, unsigned roisN, int B) {
    __shared__ unsigned mlo[PAIRS][8], mhi[PAIRS][8];
    __shared__ unsigned mloF[PAIRS][8], mhiF[PAIRS][8];
    __shared__ unsigned co[PAIRS * 8], coF[PAIRS * 8];

    int b = blockIdx.x, t = threadIdx.x;
    int lane = t & 31, warp = t >> 5;
    unsigned lt = (1u << lane) - 1u;
    int pairBase = b * (TILE / 2);

    // -------- phase 1: load pairs into registers, ballot --------
    float4 v0[PAIRS], v1[PAIRS], v2[PAIRS];
#pragma unroll
    for (int k = 0; k < PAIRS; k++) {
        int p = pairBase + k * THREADS + t;
        int r0 = 2 * p;
        float4 a = make_float4(1.f, 0.f, 0.f, 0.f);
        float4 c = make_float4(0.f, -1.f, 1.f, 0.f);
        float4 d = make_float4(0.f, 0.f, 0.f, -1.f);
        if (r0 < R) {
            const float4* g = q + (size_t)p * 3;
            a = __ldg(g + 0); c = __ldg(g + 1); d = __ldg(g + 2);
        }
        v0[k] = a; v1[k] = c; v2[k] = d;
        // pair = [cls0,b00,b01,b02 | b03,sc0, cls1,b10 | b11,b12,b13,sc1]
        bool f0 = (r0 < R)     && (c.y >= TH);
        bool f1 = (r0 + 1 < R) && (d.w >= TH);
        bool p0 = f0 && (a.x == 0.0f);
        bool p1 = f1 && (c.z == 0.0f);
        unsigned blo  = __ballot_sync(0xffffffffu, p0);
        unsigned bhi  = __ballot_sync(0xffffffffu, p1);
        unsigned bFlo = __ballot_sync(0xffffffffu, f0);
        unsigned bFhi = __ballot_sync(0xffffffffu, f1);
        if (lane == 0) {
            mlo[k][warp] = blo;   mhi[k][warp] = bhi;
            mloF[k][warp] = bFlo; mhiF[k][warp] = bFhi;
        }
    }
    __syncthreads();

    // -------- phase 2: warps 0/1 scan 16 chunks + warp-parallel lookback --------
    if (warp < 2) {
        unsigned* stat = (warp == 0) ? g_stat : g_statF;
        // 16 chunks (chunk id = k*8 + w); lanes 0..15 own one chunk each
        int k = (lane >> 3) & 1, w = lane & 7;
        unsigned cnt = 0;
        if (lane < PAIRS * 8) {
            cnt = (warp == 0)
                ? (__popc(mlo[k][w])  + __popc(mhi[k][w]))
                : (__popc(mloF[k][w]) + __popc(mhiF[k][w]));
        }
        unsigned s = cnt;
#pragma unroll
        for (int o = 1; o < 32; o <<= 1) {
            unsigned n = __shfl_up_sync(0xffffffffu, s, o);
            if (lane >= o) s += n;
        }
        unsigned agg = __shfl_sync(0xffffffffu, s, 31);

        unsigned excl = 0;
        if (b == 0) {
            if (lane == 0) atomicExch(&stat[0], FLAG_P | agg);
        } else {
            if (lane == 0) atomicExch(&stat[b], FLAG_A | agg);
            int idx = b - 1 - lane;            // lane 0 = closest predecessor
            for (;;) {
                unsigned s2;
                if (idx >= 0) {
                    do { s2 = *(volatile unsigned*)&stat[idx]; }
                    while ((s2 >> 30) == 0u);
                } else {
                    s2 = FLAG_P;
                }
                unsigned pmask = __ballot_sync(0xffffffffu, (s2 >> 30) == 2u);
                if (pmask) {
                    int first = __ffs(pmask) - 1;
                    unsigned v = (lane <= first) ? (s2 & VALMASK) : 0u;
                    excl += __reduce_add_sync(0xffffffffu, v);
                    break;
                } else {
                    excl += __reduce_add_sync(0xffffffffu, s2 & VALMASK);
                    idx -= 32;
                }
            }
            if (lane == 0) atomicExch(&stat[b], FLAG_P | (excl + agg));
        }
        if (lane < PAIRS * 8) {
            unsigned* dst = (warp == 0) ? co : coF;
            dst[lane] = excl + s - cnt;        // block-global exclusive chunk offset
        }
        if (b == B - 1 && lane == 0) {
            unsigned total = excl + agg;
            g_total[warp] = (int)total;
            out[11u * (size_t)(roisN / 5u) + warp] = (float)total;
        }
    }
    __syncthreads();

    // -------- phase 3: stable scatter from registers --------
    float2* __restrict__ outFull2 = reinterpret_cast<float2*>(out + roisN);
#pragma unroll
    for (int k = 0; k < PAIRS; k++) {
        unsigned blo  = mlo[k][warp],  bhi  = mhi[k][warp];
        unsigned bFlo = mloF[k][warp], bFhi = mhiF[k][warp];
        unsigned baseT = co[k * 8 + warp], baseF = coF[k * 8 + warp];
        unsigned preT = __popc(blo & lt) + __popc(bhi & lt);
        unsigned preF = __popc(bFlo & lt) + __popc(bFhi & lt);
        float4 a = v0[k], c = v1[k], d = v2[k];
        // row 0 of pair
        if ((bFlo >> lane) & 1u) {
            float2* oF = outFull2 + (size_t)(baseF + preF) * 3;
            oF[0] = make_float2(a.x, a.y);
            oF[1] = make_float2(a.z, a.w);
            oF[2] = make_float2(c.x, c.y);
            if ((blo >> lane) & 1u) {
                float* o = out + (size_t)(baseT + preT) * 5;
                o[0] = 0.0f; o[1] = a.y; o[2] = a.z; o[3] = a.w; o[4] = c.x;
            }
        }
        // row 1 of pair
        if ((bFhi >> lane) & 1u) {
            unsigned posF = baseF + preF + ((bFlo >> lane) & 1u);
            float2* oF = outFull2 + (size_t)posF * 3;
            oF[0] = make_float2(c.z, c.w);
            oF[1] = make_float2(d.x, d.y);
            oF[2] = make_float2(d.z, d.w);
            if ((bhi >> lane) & 1u) {
                unsigned pos = baseT + preT + ((blo >> lane) & 1u);
                float* o = out + (size_t)pos * 5;
                o[0] = 0.0f; o[1] = c.w; o[2] = d.x; o[3] = d.y; o[4] = d.z;
            }
        }
    }
}

// ---------------- K2: zero the dynamic tails + reset lookback state ----------------
__global__ void __launch_bounds__(256)
zero_tail_kernel(float* __restrict__ out, unsigned R, int B) {
    unsigned roisN = 5u * R;
    unsigned fullN = 6u * R;
    unsigned blockBase = blockIdx.x * 4096u;
    const float4 z4 = make_float4(0.f, 0.f, 0.f, 0.f);
    unsigned zsT = (unsigned)g_total[0] * 5u;
    unsigned zsF = (unsigned)g_total[1] * 6u;

#pragma unroll
    for (int j = 0; j < 4; j++) {
        unsigned f = blockBase + (unsigned)j * 1024u + threadIdx.x * 4u;
        if (f < roisN) {
            if (f + 4u <= zsT) continue;
            if (f >= zsT) {
                *reinterpret_cast<float4*>(out + f) = z4;
            } else {
                for (unsigned x = zsT; x < f + 4u; x++) out[x] = 0.0f;
            }
        } else {
            unsigned g = f - roisN;
            if (g >= fullN) continue;
            if (g + 4u <= zsF) continue;
            float* o = out + roisN;
            if (g >= zsF) {
                *reinterpret_cast<float4*>(o + g) = z4;
            } else {
                for (unsigned x = zsF; x < g + 4u; x++) o[x] = 0.0f;
            }
        }
    }
    // reset lookback statuses for the next replay
    int gi = blockIdx.x * 256 + threadIdx.x;
    if (gi < B) { g_stat[gi] = 0u; g_statF[gi] = 0u; }
}

// ---------------- launch ----------------
extern "C" void kernel_launch(void* const* d_in, const int* in_sizes, int n_in,
                              void* d_out, int out_size) {
    const float* det = (const float*)d_in[0];
    float* out = (float*)d_out;

    int R = in_sizes[0] / 6;                 // detections: (1, R, 6)
    int B = (R + TILE - 1) / TILE;           // 4096 for R = 4M
    unsigned roisN = 5u * (unsigned)R;

    fused_kernel<<<B, THREADS>>>((const float4*)det, out, R, roisN, B);

    unsigned totalFloats = 11u * (unsigned)R;
    unsigned zblocks = (totalFloats + 4095u) / 4096u;
    zero_tail_kernel<<<zblocks, 256>>>(out, (unsigned)R, B);
}

// round 8
// speedup vs baseline: 1.2561x; 1.0575x over previous
#include <cuda_runtime.h>
#include <cuda_bf16.h>
#include <stdint.h>

// ---------------- configuration ----------------
#define THREADS   256
#define TILE      1024                 // rows per block
#define PAIRS     2                    // row-pairs per thread (2*2*256 = 1024)
#define NCHUNK    (PAIRS * 8)          // 16 ballot-chunks
#define MAXB      16384
#define TH        0.35f

// packed status: [63:62]=flag (1=agg,2=prefix), [47:24]=cntF, [23:0]=cntT
#define FLAG_A64  (1ull << 62)
#define FLAG_P64  (2ull << 62)
#define PACKMASK  0x0000FFFFFFFFFFFFull

// ---------------- device scratch ----------------
__device__ unsigned long long g_stat[MAXB];   // zeroed by zero_tail for next replay
__device__ int g_total[2];

// ---------------- K1: fused count + packed-lookback scan + stable scatter ----------------
__global__ void __launch_bounds__(THREADS)
fused_kernel(const float4* __restrict__ q, float* __restrict__ out,
             int R, unsigned roisN, int B) {
    __shared__ unsigned mlo[PAIRS][8], mhi[PAIRS][8];
    __shared__ unsigned mloF[PAIRS][8], mhiF[PAIRS][8];
    __shared__ unsigned co[NCHUNK], coF[NCHUNK];

    int b = blockIdx.x, t = threadIdx.x;
    int lane = t & 31, warp = t >> 5;
    unsigned lt = (1u << lane) - 1u;
    int pairBase = b * (TILE / 2);

    // -------- phase 1: load pairs into registers, ballot --------
    float4 v0[PAIRS], v1[PAIRS], v2[PAIRS];
#pragma unroll
    for (int k = 0; k < PAIRS; k++) {
        int p = pairBase + k * THREADS + t;
        int r0 = 2 * p;
        float4 a = make_float4(1.f, 0.f, 0.f, 0.f);
        float4 c = make_float4(0.f, -1.f, 1.f, 0.f);
        float4 d = make_float4(0.f, 0.f, 0.f, -1.f);
        if (r0 < R) {
            const float4* g = q + (size_t)p * 3;
            a = __ldg(g + 0); c = __ldg(g + 1); d = __ldg(g + 2);
        }
        v0[k] = a; v1[k] = c; v2[k] = d;
        // pair = [cls0,b00,b01,b02 | b03,sc0, cls1,b10 | b11,b12,b13,sc1]
        bool f0 = (r0 < R)     && (c.y >= TH);
        bool f1 = (r0 + 1 < R) && (d.w >= TH);
        bool p0 = f0 && (a.x == 0.0f);
        bool p1 = f1 && (c.z == 0.0f);
        unsigned blo  = __ballot_sync(0xffffffffu, p0);
        unsigned bhi  = __ballot_sync(0xffffffffu, p1);
        unsigned bFlo = __ballot_sync(0xffffffffu, f0);
        unsigned bFhi = __ballot_sync(0xffffffffu, f1);
        if (lane == 0) {
            mlo[k][warp] = blo;   mhi[k][warp] = bhi;
            mloF[k][warp] = bFlo; mhiF[k][warp] = bFhi;
        }
    }
    __syncthreads();

    // -------- phase 2: warp 0 only — packed scan + single lookback walk --------
    if (warp == 0) {
        // lanes 0..15 own one chunk each (chunk id = k*8 + w)
        int k = (lane >> 3) & 1, w = lane & 7;
        unsigned cntT = 0, cntF = 0;
        if (lane < NCHUNK) {
            cntT = __popc(mlo[k][w])  + __popc(mhi[k][w]);
            cntF = __popc(mloF[k][w]) + __popc(mhiF[k][w]);
        }
        unsigned long long packed = (unsigned long long)cntT
                                  | ((unsigned long long)cntF << 24);
        // aggregate first, post FLAG_A ASAP to unblock successors
        unsigned aggT = __reduce_add_sync(0xffffffffu, cntT);
        unsigned aggF = __reduce_add_sync(0xffffffffu, cntF);
        unsigned long long aggP = (unsigned long long)aggT
                                | ((unsigned long long)aggF << 24);
        if (b == 0) {
            if (lane == 0) atomicExch(&g_stat[0], FLAG_P64 | aggP);
        } else if (lane == 0) {
            atomicExch(&g_stat[b], FLAG_A64 | aggP);
        }
        // packed inclusive shfl scan over the 16 chunks (field sums <= R < 2^24)
        unsigned long long s = packed;
#pragma unroll
        for (int o = 1; o < 32; o <<= 1) {
            unsigned long long n = __shfl_up_sync(0xffffffffu, s, o);
            if (lane >= o) s += n;
        }
        // single lookback walk (both counters at once)
        unsigned exclT = 0, exclF = 0;
        if (b > 0) {
            int idx = b - 1 - lane;            // lane 0 = closest predecessor
            for (;;) {
                unsigned long long s2;
                if (idx >= 0) {
                    do { s2 = *(volatile unsigned long long*)&g_stat[idx]; }
                    while ((s2 >> 62) == 0ull);
                } else {
                    s2 = FLAG_P64;
                }
                unsigned pmask = __ballot_sync(0xffffffffu, (s2 >> 62) == 2ull);
                unsigned vT = (unsigned)(s2 & 0xFFFFFFull);
                unsigned vF = (unsigned)((s2 >> 24) & 0xFFFFFFull);
                if (pmask) {
                    int first = __ffs(pmask) - 1;
                    if (lane > first) { vT = 0; vF = 0; }
                    exclT += __reduce_add_sync(0xffffffffu, vT);
                    exclF += __reduce_add_sync(0xffffffffu, vF);
                    break;
                } else {
                    exclT += __reduce_add_sync(0xffffffffu, vT);
                    exclF += __reduce_add_sync(0xffffffffu, vF);
                    idx -= 32;
                }
            }
            if (lane == 0) {
                unsigned long long inc = (unsigned long long)(exclT + aggT)
                                       | ((unsigned long long)(exclF + aggF) << 24);
                atomicExch(&g_stat[b], FLAG_P64 | inc);
            }
        }
        if (lane < NCHUNK) {
            unsigned sT = (unsigned)(s & 0xFFFFFFull);
            unsigned sF = (unsigned)((s >> 24) & 0xFFFFFFull);
            co [lane] = exclT + sT - cntT;     // block-global exclusive offsets
            coF[lane] = exclF + sF - cntF;
        }
        if (b == B - 1 && lane == 0) {
            g_total[0] = (int)(exclT + aggT);
            g_total[1] = (int)(exclF + aggF);
            out[11u * (size_t)(roisN / 5u) + 0] = (float)(exclT + aggT);
            out[11u * (size_t)(roisN / 5u) + 1] = (float)(exclF + aggF);
        }
    }
    __syncthreads();

    // -------- phase 3: stable scatter from registers --------
    float2* __restrict__ outFull2 = reinterpret_cast<float2*>(out + roisN);
#pragma unroll
    for (int k = 0; k < PAIRS; k++) {
        unsigned blo  = mlo[k][warp],  bhi  = mhi[k][warp];
        unsigned bFlo = mloF[k][warp], bFhi = mhiF[k][warp];
        unsigned baseT = co[k * 8 + warp], baseF = coF[k * 8 + warp];
        unsigned preT = __popc(blo & lt) + __popc(bhi & lt);
        unsigned preF = __popc(bFlo & lt) + __popc(bFhi & lt);
        float4 a = v0[k], c = v1[k], d = v2[k];
        // row 0 of pair
        if ((bFlo >> lane) & 1u) {
            float2* oF = outFull2 + (size_t)(baseF + preF) * 3;
            oF[0] = make_float2(a.x, a.y);
            oF[1] = make_float2(a.z, a.w);
            oF[2] = make_float2(c.x, c.y);
            if ((blo >> lane) & 1u) {
                float* o = out + (size_t)(baseT + preT) * 5;
                o[0] = 0.0f; o[1] = a.y; o[2] = a.z; o[3] = a.w; o[4] = c.x;
            }
        }
        // row 1 of pair
        if ((bFhi >> lane) & 1u) {
            unsigned posF = baseF + preF + ((bFlo >> lane) & 1u);
            float2* oF = outFull2 + (size_t)posF * 3;
            oF[0] = make_float2(c.z, c.w);
            oF[1] = make_float2(d.x, d.y);
            oF[2] = make_float2(d.z, d.w);
            if ((bhi >> lane) & 1u) {
                unsigned pos = baseT + preT + ((blo >> lane) & 1u);
                float* o = out + (size_t)pos * 5;
                o[0] = 0.0f; o[1] = c.w; o[2] = d.x; o[3] = d.y; o[4] = d.z;
            }
        }
    }
}

// ---------------- K2: zero the dynamic tails + reset lookback state ----------------
__global__ void __launch_bounds__(256)
zero_tail_kernel(float* __restrict__ out, unsigned R, int B) {
    unsigned roisN = 5u * R;
    unsigned fullN = 6u * R;
    unsigned blockBase = blockIdx.x * 4096u;
    const float4 z4 = make_float4(0.f, 0.f, 0.f, 0.f);
    unsigned zsT = (unsigned)g_total[0] * 5u;
    unsigned zsF = (unsigned)g_total[1] * 6u;

#pragma unroll
    for (int j = 0; j < 4; j++) {
        unsigned f = blockBase + (unsigned)j * 1024u + threadIdx.x * 4u;
        if (f < roisN) {
            if (f + 4u <= zsT) continue;
            if (f >= zsT) {
                *reinterpret_cast<float4*>(out + f) = z4;
            } else {
                for (unsigned x = zsT; x < f + 4u; x++) out[x] = 0.0f;
            }
        } else {
            unsigned g = f - roisN;
            if (g >= fullN) continue;
            if (g + 4u <= zsF) continue;
            float* o = out + roisN;
            if (g >= zsF) {
                *reinterpret_cast<float4*>(o + g) = z4;
            } else {
                for (unsigned x = zsF; x < g + 4u; x++) o[x] = 0.0f;
            }
        }
    }
    // reset lookback statuses for the next replay
    int gi = blockIdx.x * 256 + threadIdx.x;
    if (gi < B) g_stat[gi] = 0ull;
}

// ---------------- launch ----------------
extern "C" void kernel_launch(void* const* d_in, const int* in_sizes, int n_in,
                              void* d_out, int out_size) {
    const float* det = (const float*)d_in[0];
    float* out = (float*)d_out;

    int R = in_sizes[0] / 6;                 // detections: (1, R, 6)
    int B = (R + TILE - 1) / TILE;           // 4096 for R = 4M
    unsigned roisN = 5u * (unsigned)R;

    fused_kernel<<<B, THREADS>>>((const float4*)det, out, R, roisN, B);

    unsigned totalFloats = 11u * (unsigned)R;
    unsigned zblocks = (totalFloats + 4095u) / 4096u;
    zero_tail_kernel<<<zblocks, 256>>>(out, (unsigned)R, B);
}

// round 9
// speedup vs baseline: 1.2574x; 1.0010x over previous
#include <cuda_runtime.h>
#include <cuda_bf16.h>
#include <stdint.h>

// ---------------- configuration ----------------
#define THREADS   256
#define TILE      1024                 // rows per block
#define PAIRS     2                    // row-pairs per thread (2*2*256 = 1024)
#define NCHUNK    (PAIRS * 8)          // 16 ballot-chunks
#define MAXB      16384
#define TH        0.35f

// packed status: [63:62]=flag (1=agg,2=prefix), [47:24]=cntF, [23:0]=cntT
#define FLAG_A64  (1ull << 62)
#define FLAG_P64  (2ull << 62)

// ---------------- device scratch ----------------
__device__ unsigned long long g_stat[MAXB];   // reset by reset_kernel each call

// block-cooperative zero of float range [s, e) relative to base
__device__ __forceinline__ void zero_range(float* __restrict__ base,
                                           unsigned s, unsigned e, int t) {
    const float4 z4 = make_float4(0.f, 0.f, 0.f, 0.f);
    unsigned q0 = s & ~3u;
    for (unsigned qf = q0 + (unsigned)t * 4u; qf < e; qf += THREADS * 4u) {
        unsigned lo = qf > s ? qf : s;
        unsigned hi = (qf + 4u < e) ? qf + 4u : e;
        if (lo == qf && hi == qf + 4u) {
            *reinterpret_cast<float4*>(base + qf) = z4;
        } else {
            for (unsigned x = lo; x < hi; x++) base[x] = 0.0f;
        }
    }
}

// ---------------- K1: fully fused count + lookback + scatter + slack-zero ----------------
__global__ void __launch_bounds__(THREADS)
fused_kernel(const float4* __restrict__ q, float* __restrict__ out,
             int R, unsigned roisN, int B) {
    __shared__ unsigned mlo[PAIRS][8], mhi[PAIRS][8];
    __shared__ unsigned mloF[PAIRS][8], mhiF[PAIRS][8];
    __shared__ unsigned co[NCHUNK], coF[NCHUNK];
    __shared__ unsigned sAgg[2];       // aggT, aggF

    int b = blockIdx.x, t = threadIdx.x;
    int lane = t & 31, warp = t >> 5;
    unsigned lt = (1u << lane) - 1u;
    int pairBase = b * (TILE / 2);

    // -------- phase 1: load pairs into registers, ballot --------
    float4 v0[PAIRS], v1[PAIRS], v2[PAIRS];
#pragma unroll
    for (int k = 0; k < PAIRS; k++) {
        int p = pairBase + k * THREADS + t;
        int r0 = 2 * p;
        float4 a = make_float4(1.f, 0.f, 0.f, 0.f);
        float4 c = make_float4(0.f, -1.f, 1.f, 0.f);
        float4 d = make_float4(0.f, 0.f, 0.f, -1.f);
        if (r0 < R) {
            const float4* g = q + (size_t)p * 3;
            a = __ldg(g + 0); c = __ldg(g + 1); d = __ldg(g + 2);
        }
        v0[k] = a; v1[k] = c; v2[k] = d;
        // pair = [cls0,b00,b01,b02 | b03,sc0, cls1,b10 | b11,b12,b13,sc1]
        bool f0 = (r0 < R)     && (c.y >= TH);
        bool f1 = (r0 + 1 < R) && (d.w >= TH);
        bool p0 = f0 && (a.x == 0.0f);
        bool p1 = f1 && (c.z == 0.0f);
        unsigned blo  = __ballot_sync(0xffffffffu, p0);
        unsigned bhi  = __ballot_sync(0xffffffffu, p1);
        unsigned bFlo = __ballot_sync(0xffffffffu, f0);
        unsigned bFhi = __ballot_sync(0xffffffffu, f1);
        if (lane == 0) {
            mlo[k][warp] = blo;   mhi[k][warp] = bhi;
            mloF[k][warp] = bFlo; mhiF[k][warp] = bFhi;
        }
    }
    __syncthreads();

    // -------- phase 2: warp 0 — packed scan + single lookback walk --------
    if (warp == 0) {
        int k = (lane >> 3) & 1, w = lane & 7;
        unsigned cntT = 0, cntF = 0;
        if (lane < NCHUNK) {
            cntT = __popc(mlo[k][w])  + __popc(mhi[k][w]);
            cntF = __popc(mloF[k][w]) + __popc(mhiF[k][w]);
        }
        unsigned long long packed = (unsigned long long)cntT
                                  | ((unsigned long long)cntF << 24);
        unsigned aggT = __reduce_add_sync(0xffffffffu, cntT);
        unsigned aggF = __reduce_add_sync(0xffffffffu, cntF);
        unsigned long long aggP = (unsigned long long)aggT
                                | ((unsigned long long)aggF << 24);
        if (b == 0) {
            if (lane == 0) atomicExch(&g_stat[0], FLAG_P64 | aggP);
        } else if (lane == 0) {
            atomicExch(&g_stat[b], FLAG_A64 | aggP);
        }
        unsigned long long s = packed;
#pragma unroll
        for (int o = 1; o < 32; o <<= 1) {
            unsigned long long n = __shfl_up_sync(0xffffffffu, s, o);
            if (lane >= o) s += n;
        }
        unsigned exclT = 0, exclF = 0;
        if (b > 0) {
            int idx = b - 1 - lane;
            for (;;) {
                unsigned long long s2;
                if (idx >= 0) {
                    do { s2 = *(volatile unsigned long long*)&g_stat[idx]; }
                    while ((s2 >> 62) == 0ull);
                } else {
                    s2 = FLAG_P64;
                }
                unsigned pmask = __ballot_sync(0xffffffffu, (s2 >> 62) == 2ull);
                unsigned vT = (unsigned)(s2 & 0xFFFFFFull);
                unsigned vF = (unsigned)((s2 >> 24) & 0xFFFFFFull);
                if (pmask) {
                    int first = __ffs(pmask) - 1;
                    if (lane > first) { vT = 0; vF = 0; }
                    exclT += __reduce_add_sync(0xffffffffu, vT);
                    exclF += __reduce_add_sync(0xffffffffu, vF);
                    break;
                } else {
                    exclT += __reduce_add_sync(0xffffffffu, vT);
                    exclF += __reduce_add_sync(0xffffffffu, vF);
                    idx -= 32;
                }
            }
            if (lane == 0) {
                unsigned long long inc = (unsigned long long)(exclT + aggT)
                                       | ((unsigned long long)(exclF + aggF) << 24);
                atomicExch(&g_stat[b], FLAG_P64 | inc);
            }
        }
        if (lane < NCHUNK) {
            unsigned sT = (unsigned)(s & 0xFFFFFFull);
            unsigned sF = (unsigned)((s >> 24) & 0xFFFFFFull);
            co [lane] = exclT + sT - cntT;
            coF[lane] = exclF + sF - cntF;
        }
        if (lane == 0) { sAgg[0] = aggT; sAgg[1] = aggF; }
        if (b == B - 1 && lane == 0) {
            out[11u * (size_t)(roisN / 5u) + 0] = (float)(exclT + aggT);
            out[11u * (size_t)(roisN / 5u) + 1] = (float)(exclF + aggF);
        }
    }
    __syncthreads();

    // -------- phase 3: stable scatter from registers --------
    float2* __restrict__ outFull2 = reinterpret_cast<float2*>(out + roisN);
#pragma unroll
    for (int k = 0; k < PAIRS; k++) {
        unsigned blo  = mlo[k][warp],  bhi  = mhi[k][warp];
        unsigned bFlo = mloF[k][warp], bFhi = mhiF[k][warp];
        unsigned baseT = co[k * 8 + warp], baseF = coF[k * 8 + warp];
        unsigned preT = __popc(blo & lt) + __popc(bhi & lt);
        unsigned preF = __popc(bFlo & lt) + __popc(bFhi & lt);
        float4 a = v0[k], c = v1[k], d = v2[k];
        // row 0 of pair
        if ((bFlo >> lane) & 1u) {
            float2* oF = outFull2 + (size_t)(baseF + preF) * 3;
            oF[0] = make_float2(a.x, a.y);
            oF[1] = make_float2(a.z, a.w);
            oF[2] = make_float2(c.x, c.y);
            if ((blo >> lane) & 1u) {
                float* o = out + (size_t)(baseT + preT) * 5;
                o[0] = 0.0f; o[1] = a.y; o[2] = a.z; o[3] = a.w; o[4] = c.x;
            }
        }
        // row 1 of pair
        if ((bFhi >> lane) & 1u) {
            unsigned posF = baseF + preF + ((bFlo >> lane) & 1u);
            float2* oF = outFull2 + (size_t)posF * 3;
            oF[0] = make_float2(c.z, c.w);
            oF[1] = make_float2(d.x, d.y);
            oF[2] = make_float2(d.z, d.w);
            if ((bhi >> lane) & 1u) {
                unsigned pos = baseT + preT + ((blo >> lane) & 1u);
                float* o = out + (size_t)pos * 5;
                o[0] = 0.0f; o[1] = c.w; o[2] = d.x; o[3] = d.y; o[4] = d.z;
            }
        }
    }

    // -------- phase 4: zero this block's slack slices (disjoint from all scatter) --------
    {
        unsigned Ru = (unsigned)R;
        unsigned tileStart = (unsigned)b * TILE;
        unsigned procEnd = tileStart + TILE < Ru ? tileStart + TILE : Ru;
        unsigned exclT = co[0],  exclF = coF[0];
        unsigned incT  = exclT + sAgg[0];
        unsigned incF  = exclF + sAgg[1];
        // rois: zero rows [R - slackB_T, R - slackA_T)
        unsigned slackA = tileStart - exclT;
        unsigned slackB = procEnd   - incT;
        zero_range(out, (Ru - slackB) * 5u, (Ru - slackA) * 5u, t);
        // rois_full: zero rows [R - slackB_F, R - slackA_F)
        unsigned fslackA = tileStart - exclF;
        unsigned fslackB = procEnd   - incF;
        zero_range(out + roisN, (Ru - fslackB) * 6u, (Ru - fslackA) * 6u, t);
    }
}

// ---------------- K2: reset lookback statuses for the next replay ----------------
__global__ void reset_kernel(int B) {
    int i = blockIdx.x * blockDim.x + threadIdx.x;
    if (i < B) g_stat[i] = 0ull;
}

// ---------------- launch ----------------
extern "C" void kernel_launch(void* const* d_in, const int* in_sizes, int n_in,
                              void* d_out, int out_size) {
    const float* det = (const float*)d_in[0];
    float* out = (float*)d_out;

    int R = in_sizes[0] / 6;                 // detections: (1, R, 6)
    int B = (R + TILE - 1) / TILE;           // 4096 for R = 4M
    unsigned roisN = 5u * (unsigned)R;

    fused_kernel<<<B, THREADS>>>((const float4*)det, out, R, roisN, B);
    reset_kernel<<<(B + 255) / 256, 256>>>(B);
}